// round 15
// baseline (speedup 1.0000x reference)
#include <cuda_runtime.h>
#include <cuda_bf16.h>
#include <cstdint>

#define Bb   64
#define Nn   1024
#define G3H  768
#define LMAX 192
#define TT   16

// Precomputed scratch (allocation-free __device__ globals)
__device__ float g_TE[300 * G3H];       // type_emb @ w_ih^T
__device__ float g_POS[1000 * G3H];     // pos_table @ w_ih^T
__device__ int2  g_ordIP[Bb * Nn];      // per batch: (node, parent) sorted by level
__device__ int   g_ordTP[Bb * Nn];      // (type<<16)|cpos of ordered node
__device__ int   g_lstart[Bb][LMAX + 1];
__device__ int   g_clstart[16][LMAX + 1];
__device__ int4  g_ordC[16 * 4096];     // cluster-fused: (node,parent,batch,tp)

// ---------------------------------------------------------------------------
__global__ void proj_kernel(const float* __restrict__ A, const float* __restrict__ W,
                            int rows, int which)
{
    __shared__ float As[8][256];
    float* outp = which ? g_POS : g_TE;
    int r0 = blockIdx.x * 8;
    int j  = blockIdx.y * 128 + threadIdx.x;

    for (int idx = threadIdx.x; idx < 2048; idx += 128) {
        int rr = idx >> 8, kk = idx & 255;
        As[rr][kk] = (r0 + rr < rows) ? A[(r0 + rr) * 256 + kk] : 0.f;
    }
    __syncthreads();

    float acc[8] = {0, 0, 0, 0, 0, 0, 0, 0};
    const float4* W4 = (const float4*)W + j * 64;
#pragma unroll 8
    for (int kc = 0; kc < 64; kc++) {
        float4 w = W4[kc];
#pragma unroll
        for (int rr = 0; rr < 8; rr++) {
            acc[rr] = fmaf(w.x, As[rr][kc * 4 + 0], acc[rr]);
            acc[rr] = fmaf(w.y, As[rr][kc * 4 + 1], acc[rr]);
            acc[rr] = fmaf(w.z, As[rr][kc * 4 + 2], acc[rr]);
            acc[rr] = fmaf(w.w, As[rr][kc * 4 + 3], acc[rr]);
        }
    }
#pragma unroll
    for (int rr = 0; rr < 8; rr++)
        if (r0 + rr < rows) outp[(r0 + rr) * G3H + j] = acc[rr];
}

// ---------------------------------------------------------------------------
__global__ void embed_kernel(const int* __restrict__ types, const int* __restrict__ vals,
                             const int* __restrict__ cpos,
                             const float* __restrict__ te, const float* __restrict__ pos,
                             const float* __restrict__ tok, float* __restrict__ out)
{
    int sub = threadIdx.x >> 6;
    int t   = threadIdx.x & 63;
    int n   = blockIdx.x * 4 + sub;
    int b   = blockIdx.y;
    int idx = b * Nn + n;

    int typ = types[idx];
    int p   = cpos[idx];
    int v0  = vals[2 * idx];
    int v1  = vals[2 * idx + 1];

    const float4* te4 = (const float4*)te;
    const float4* pp4 = (const float4*)pos;
    const float4* tk4 = (const float4*)tok;

    float4 e  = te4[typ * 64 + t];
    float4 pv = pp4[(size_t)p * 64 + t];
    float4 t0 = tk4[(size_t)v0 * 64 + t];
    float4 t1 = tk4[(size_t)v1 * 64 + t];

    float4 o;
    o.x = 4.f * e.x + 0.25f * pv.x + 2.f * (t0.x + t1.x);
    o.y = 4.f * e.y + 0.25f * pv.y + 2.f * (t0.y + t1.y);
    o.z = 4.f * e.z + 0.25f * pv.z + 2.f * (t0.z + t1.z);
    o.w = 4.f * e.w + 0.25f * pv.w + 2.f * (t0.w + t1.w);

    ((float4*)out)[((size_t)n * Bb + b) * 128 + t] = o;
}

// ---------------------------------------------------------------------------
__global__ void level_kernel(const int* __restrict__ lpi, const int* __restrict__ types,
                             const int* __restrict__ cpos)
{
    __shared__ int sL[Nn];
    __shared__ unsigned short sLev[Nn];
    __shared__ int cnt[LMAX];
    __shared__ int off[LMAX + 1];

    int b = blockIdx.x, tid = threadIdx.x;
    for (int i = tid; i < Nn; i += 256) sL[i] = lpi[b * Nn + i];
    for (int i = tid; i < LMAX; i += 256) cnt[i] = 0;
    __syncthreads();

    for (int i = tid; i < Nn; i += 256) {
        int d = 0, p = i;
        while (p > 0 && d < LMAX - 1) { p = sL[p]; d++; }
        sLev[i] = (unsigned short)d;
        atomicAdd(&cnt[d], 1);
    }
    __syncthreads();

    if (tid == 0) {
        int acc = 0;
        for (int l = 0; l < LMAX; l++) { off[l] = acc; acc += cnt[l]; }
        off[LMAX] = acc;
    }
    __syncthreads();

    for (int l = tid; l <= LMAX; l += 256) g_lstart[b][l] = off[l];
    __syncthreads();

    for (int i = tid; i < Nn; i += 256) {
        int l = sLev[i];
        int pos = atomicAdd(&off[l], 1);
        int par = (i == 0) ? -1 : sL[i];
        g_ordIP[b * Nn + pos] = make_int2(i, par);
        g_ordTP[b * Nn + pos] = (types[b * Nn + i] << 16) | cpos[b * Nn + i];
    }
}

// ---------------------------------------------------------------------------
__global__ void merge_kernel()
{
    __shared__ int sLs[4][LMAX + 1];
    __shared__ int cls[LMAX + 1];
    int c = blockIdx.x, tid = threadIdx.x;

    for (int idx = tid; idx < 4 * (LMAX + 1); idx += 256)
        sLs[idx / (LMAX + 1)][idx % (LMAX + 1)] = g_lstart[c * 4 + idx / (LMAX + 1)][idx % (LMAX + 1)];
    __syncthreads();

    if (tid == 0) {
        int acc = 0;
        for (int l = 0; l < LMAX; l++) {
            cls[l] = acc;
            for (int b = 0; b < 4; b++) acc += sLs[b][l + 1] - sLs[b][l];
        }
        cls[LMAX] = acc;
    }
    __syncthreads();

    for (int l = tid; l <= LMAX; l += 256) g_clstart[c][l] = cls[l];

    for (int l = 0; l < LMAX; l++) {
        int base = cls[l];
        for (int b = 0; b < 4; b++) {
            int gb = c * 4 + b;
            int s = sLs[b][l], e = sLs[b][l + 1];
            for (int k = s + tid; k < e; k += 256) {
                int2 ip = g_ordIP[gb * Nn + k];
                int tp  = g_ordTP[gb * Nn + k];
                g_ordC[c * 4096 + base + (k - s)] = make_int4(ip.x, ip.y, b, tp);
            }
            base += e - s;
        }
    }
}

// ---------------------------------------------------------------------------
__device__ __forceinline__ void ffma2(unsigned long long& d,
                                      unsigned long long a, unsigned long long b)
{
    asm("fma.rn.f32x2 %0, %1, %2, %0;" : "+l"(d) : "l"(a), "l"(b));
}
__device__ __forceinline__ float2 unpk(unsigned long long v)
{
    float2 r; asm("mov.b64 {%0, %1}, %2;" : "=f"(r.x), "=f"(r.y) : "l"(v)); return r;
}
__device__ __forceinline__ void cpa16(uint32_t smem, const void* g)
{
    asm volatile("cp.async.cg.shared.global [%0], [%1], 16;" :: "r"(smem), "l"(g) : "memory");
}
__device__ __forceinline__ void cpa_commit() { asm volatile("cp.async.commit_group;" ::: "memory"); }
__device__ __forceinline__ void cpa_wait0()  { asm volatile("cp.async.wait_group 0;"  ::: "memory"); }

// dynamic smem layout (bytes)
#define PB_OFF   0            // float4 PB[2][16*68]  = 34816
#define GH_OFF   34816        // float  GH[16*97]     = 6208
#define SGI_OFF  41024        // float  SGI[16*192]   = 12288
#define SIDX_OFF 53312        // int4   sIdx[3*16]    = 768
#define SBIH_OFF 54080        // float  sBih[96]      = 384
#define SMX_OFF  54464        // int    sGmax         = 4
#define DSMEM    54528

// ---------------------------------------------------------------------------
// Level-parallel GRU, cp.async-pipelined. 16 clusters x 8 CTAs.
// Tile t: issue gi(t) + parents(t+1) via cp.async, matvec 16 nodes on PB[buf],
// wait, combine 512 items (warp = node slice), store. Parents of a level-l
// node are level l-1 => prefetch across tiles is always safe within a level.
// ---------------------------------------------------------------------------
__global__ void __cluster_dims__(8, 1, 1) __launch_bounds__(384, 1)
scan_kernel(const float* __restrict__ bih_g, const float* __restrict__ bhh_g,
            const float* __restrict__ whh, float* __restrict__ out)
{
    extern __shared__ char dsm[];
    float4* PB   = (float4*)(dsm + PB_OFF);     // [2][16*68]
    float*  GH   = (float*)(dsm + GH_OFF);      // [16*97]
    float*  SGI  = (float*)(dsm + SGI_OFF);     // [16*192]
    int4*   sIdx = (int4*)(dsm + SIDX_OFF);     // [3*16], slot-major
    float*  sBih = (float*)(dsm + SBIH_OFF);    // [96]
    int*    sGmx = (int*)(dsm + SMX_OFF);

    const int tid  = threadIdx.x;
    const int rank = blockIdx.x & 7;
    const int cid  = blockIdx.x >> 3;

    // matvec role
    const int j    = tid >> 2;
    const int q    = tid & 3;
    const int grow = ((j >> 5) << 8) + (rank << 5) + (j & 31);
    const float bhh = bhh_g[grow];

    const uint32_t pb_s  = (uint32_t)__cvta_generic_to_shared(PB);
    const uint32_t sgi_s = (uint32_t)__cvta_generic_to_shared(SGI);

    ulonglong2 Wreg[16];
    {
        const ulonglong2* wp = (const ulonglong2*)(whh + (size_t)grow * 256 + q * 64);
#pragma unroll
        for (int t = 0; t < 16; t++) Wreg[t] = wp[t];
    }

    if (tid < 96) sBih[tid] = bih_g[(tid >> 5) * 256 + (rank << 5) + (tid & 31)];
    if (tid == 0) {
        int gm = 0;
        for (int l = LMAX - 1; l >= 0; l--)
            if (g_clstart[cid][l] < 4096) { gm = l; break; }
        *sGmx = gm;
    }
    __syncthreads();
    const int gmax = *sGmx;

    const float* outF = out;
    const int4*  ord  = g_ordC + cid * 4096;

    for (int lev = 0; lev <= gmax; lev++) {
        const int s = g_clstart[cid][lev], e = g_clstart[cid][lev + 1];
        if (s < e) {
            // ---- level prologue: idx slots 0,1 + parents of tile 0 ----
            if (tid < 32) {
                int p = s + tid;
                sIdx[(tid >> 4) * TT + (tid & 15)] =
                    (p < e) ? ord[p] : make_int4(0, -2, 0, 0);
            }
            __syncthreads();
            for (int idx = tid; idx < TT * 64; idx += 384) {
                int n = idx >> 6, kc = idx & 63;
                int4 en = sIdx[n];
                uint32_t dst = pb_s + (uint32_t)((n * 68 + (kc >> 4) * 17 + (kc & 15)) * 16);
                if (en.y >= 0)
                    cpa16(dst, outF + ((size_t)en.y * Bb + (cid * 4 + en.z)) * 512 + 256 + kc * 4);
                else
                    *(float4*)(dsm + PB_OFF + (n * 68 + (kc >> 4) * 17 + (kc & 15)) * 16) =
                        make_float4(0.f, 0.f, 0.f, 0.f);
            }
            cpa_commit(); cpa_wait0();
            __syncthreads();

            int buf = 0;
            for (int t0 = s, kt = 0; t0 < e; t0 += TT, kt++, buf ^= 1) {
                const int  nt    = min(TT, e - t0);
                const bool more1 = (t0 + TT < e);
                const int  slot0 = (kt % 3) * TT;
                const int  slot1 = ((kt + 1) % 3) * TT;
                const int  slot2 = ((kt + 2) % 3) * TT;

                // issue gi(t) into SGI: 768 16B chunks
                for (int c = tid; c < 768; c += 384) {
                    int n = c / 48, rem = c - n * 48;
                    int r = rem >> 3, k = rem & 7;
                    int gate = r >> 1, src = r & 1;
                    int tp = sIdx[slot0 + n].w;
                    const float* g = src ? (g_POS + (size_t)(tp & 0xffff) * G3H)
                                         : (g_TE  + (size_t)(unsigned)(tp >> 16) * G3H);
                    cpa16(sgi_s + (uint32_t)((n * 192 + gate * 64 + src * 32 + k * 4) * 4),
                          g + gate * 256 + (rank << 5) + k * 4);
                }
                // issue parents(t+1) into PB[buf^1]
                if (more1) {
                    for (int idx = tid; idx < TT * 64; idx += 384) {
                        int n = idx >> 6, kc = idx & 63;
                        int4 en = sIdx[slot1 + n];
                        int off4 = (buf ^ 1) * 1088 + n * 68 + (kc >> 4) * 17 + (kc & 15);
                        if (en.y >= 0)
                            cpa16(pb_s + (uint32_t)(off4 * 16),
                                  outF + ((size_t)en.y * Bb + (cid * 4 + en.z)) * 512 + 256 + kc * 4);
                        else
                            *(float4*)(dsm + PB_OFF + off4 * 16) = make_float4(0.f, 0.f, 0.f, 0.f);
                    }
                }
                cpa_commit();

                // idx for tile t+2
                int4 id2;
                if (tid < 16) {
                    int p = t0 + 2 * TT + tid;
                    id2 = (p < e) ? ord[p] : make_int4(0, -2, 0, 0);
                }

                // ---- matvec: 16 nodes on PB[buf] ----
                const float4* PBb = PB + buf * 1088;
#pragma unroll
                for (int n = 0; n < TT; n++) {
                    unsigned long long a0 = 0ull, a1 = 0ull;
                    const ulonglong2* hb = (const ulonglong2*)(PBb + n * 68 + q * 17);
#pragma unroll
                    for (int t = 0; t < 16; t++) {
                        ulonglong2 h2 = hb[t];
                        ffma2(a0, Wreg[t].x, h2.x);
                        ffma2(a1, Wreg[t].y, h2.y);
                    }
                    float2 u = unpk(a0), v = unpk(a1);
                    float sv = (u.x + u.y) + (v.x + v.y);
                    sv += __shfl_xor_sync(0xffffffffu, sv, 1);
                    sv += __shfl_xor_sync(0xffffffffu, sv, 2);
                    if (q == (n & 3)) GH[n * 97 + j] = sv + bhh;
                }

                if (tid < 16) sIdx[slot2 + tid] = id2;
                cpa_wait0();
                __syncthreads();

                // ---- combine: 512 items (n, cc); warp = one node slice ----
#pragma unroll
                for (int it = 0; it < 2; it++) {
                    int idx = tid + it * 384;
                    if (idx < 512) {
                        int n = idx >> 5, cc = idx & 31;
                        if (n < nt) {
                            int4 en = sIdx[slot0 + n];
                            const float* gi = SGI + n * 192;
                            float gir = fmaf(4.f, gi[cc],        fmaf(0.25f, gi[32 + cc],  sBih[cc]));
                            float giz = fmaf(4.f, gi[64 + cc],   fmaf(0.25f, gi[96 + cc],  sBih[32 + cc]));
                            float gin = fmaf(4.f, gi[128 + cc],  fmaf(0.25f, gi[160 + cc], sBih[64 + cc]));
                            float ghr = GH[n * 97 + cc];
                            float ghz = GH[n * 97 + 32 + cc];
                            float ghn = GH[n * 97 + 64 + cc];
                            float r = 1.f / (1.f + __expf(-(gir + ghr)));
                            float z = 1.f / (1.f + __expf(-(giz + ghz)));
                            float na = gin + r * ghn;
                            float th; asm("tanh.approx.f32 %0, %1;" : "=f"(th) : "f"(na));
                            int cg = (rank << 5) + cc;
                            float hp = ((const float*)(PB + buf * 1088))
                                       [(n * 68 + (cg >> 6) * 17 + ((cg >> 2) & 15)) * 4 + (cg & 3)];
                            float h = (1.f - z) * th + z * hp;
                            __stcg(&out[((size_t)en.x * Bb + (cid * 4 + en.z)) * 512 + 256 + cg], h);
                        }
                    }
                }
                __syncthreads();
            }
        }
        asm volatile("barrier.cluster.arrive.aligned;" ::: "memory");
        asm volatile("barrier.cluster.wait.aligned;" ::: "memory");
    }
}

// ---------------------------------------------------------------------------
extern "C" void kernel_launch(void* const* d_in, const int* in_sizes, int n_in,
                              void* d_out, int out_size)
{
    const int*   types = (const int*)d_in[0];
    const int*   vals  = (const int*)d_in[1];
    /* d_in[2] = node_val_offsets: fixed arange*2, unused */
    const int*   lpi   = (const int*)d_in[3];
    const int*   cposi = (const int*)d_in[4];
    const float* te    = (const float*)d_in[5];
    const float* pos   = (const float*)d_in[6];
    const float* tok   = (const float*)d_in[7];
    const float* wih   = (const float*)d_in[8];
    const float* whh   = (const float*)d_in[9];
    const float* bih   = (const float*)d_in[10];
    const float* bhh   = (const float*)d_in[11];
    float* out = (float*)d_out;
    (void)in_sizes; (void)n_in; (void)out_size;

    level_kernel<<<64, 256>>>(lpi, types, cposi);
    merge_kernel<<<16, 256>>>();
    proj_kernel<<<dim3(38, 6), 128>>>(te, wih, 300, 0);
    proj_kernel<<<dim3(125, 6), 128>>>(pos, wih, 1000, 1);
    embed_kernel<<<dim3(256, 64), 256>>>(types, vals, cposi, te, pos, tok, out);

    cudaFuncSetAttribute(scan_kernel, cudaFuncAttributeMaxDynamicSharedMemorySize, DSMEM);
    scan_kernel<<<128, 384, DSMEM>>>(bih, bhh, whh, out);
}